// round 1
// baseline (speedup 1.0000x reference)
#include <cuda_runtime.h>
#include <math.h>

#define B_    4
#define NTOK  8192
#define D_    512
#define H_    8
#define DH_   64
#define MLM   256
#define LSEG  32
#define BH    (B_*H_)
#define KER_  33

// ---------------- scratch buffers ----------------
__device__ float g_normed[(size_t)B_*NTOK*D_];
__device__ float g_q [(size_t)BH*NTOK*DH_];
__device__ float g_k [(size_t)BH*NTOK*DH_];
__device__ float g_v [(size_t)BH*NTOK*DH_];
__device__ float g_ql[(size_t)BH*MLM*DH_];
__device__ float g_kl[(size_t)BH*MLM*DH_];
__device__ float g_X [(size_t)BH*MLM*MLM];
__device__ float g_Za[(size_t)BH*MLM*MLM];
__device__ float g_Zb[(size_t)BH*MLM*MLM];
__device__ float g_XZ[(size_t)BH*MLM*MLM];
__device__ float g_W [(size_t)BH*MLM*MLM];
__device__ float g_W2[(size_t)BH*MLM*MLM];
__device__ float g_A3V[(size_t)BH*MLM*DH_];
__device__ float g_Y  [(size_t)BH*MLM*DH_];
__device__ float g_O  [(size_t)B_*NTOK*D_];
__device__ unsigned g_maxbits[2];

// ---------------- LayerNorm ----------------
__global__ void ln_kernel(const float* __restrict__ x, const float* __restrict__ gamma,
                          const float* __restrict__ beta, float* __restrict__ out) {
    int row = blockIdx.x;
    int tid = threadIdx.x;                 // 256 threads, 2 elems each
    const float* xr = x + (size_t)row * D_;
    float v0 = xr[tid], v1 = xr[tid + 256];
    float s = v0 + v1, s2 = v0*v0 + v1*v1;
    #pragma unroll
    for (int o = 16; o > 0; o >>= 1) {
        s  += __shfl_xor_sync(0xffffffffu, s,  o);
        s2 += __shfl_xor_sync(0xffffffffu, s2, o);
    }
    __shared__ float sh[16];
    int w = tid >> 5, l = tid & 31;
    if (l == 0) { sh[w] = s; sh[w + 8] = s2; }
    __syncthreads();
    if (tid == 0) {
        float a = 0.f, b2 = 0.f;
        #pragma unroll
        for (int i = 0; i < 8; i++) { a += sh[i]; b2 += sh[i + 8]; }
        sh[0] = a; sh[8] = b2;
    }
    __syncthreads();
    float mu  = sh[0] * (1.f / D_);
    float var = sh[8] * (1.f / D_) - mu * mu;
    float inv = rsqrtf(var + 1e-5f);
    float* orow = out + (size_t)row * D_;
    orow[tid]       = (v0 - mu) * inv * gamma[tid]       + beta[tid];
    orow[tid + 256] = (v1 - mu) * inv * gamma[tid + 256] + beta[tid + 256];
}

// ---------------- SGEMM 128x128x8, 256 thr, 8x8 micro-tile ----------------
// mode 0: C = alpha*(A@B)
// mode 1: qkv scatter into q/k/v head layout (q scaled by 1/8)
// mode 2: C = A@B + bias[col] + addx[elem]   (final out-proj + residual)
__global__ void __launch_bounds__(256) sgemm_kernel(
        const float* __restrict__ A, const float* __restrict__ B, float* __restrict__ C,
        int M, int N, int K, size_t sA, size_t sB, size_t sC,
        float alpha, int mode,
        const float* __restrict__ addx, const float* __restrict__ bias,
        float* __restrict__ qp, float* __restrict__ kp, float* __restrict__ vp)
{
    int bz = blockIdx.z;
    A += (size_t)bz * sA; B += (size_t)bz * sB; C += (size_t)bz * sC;
    int m0 = blockIdx.y * 128, n0 = blockIdx.x * 128;
    __shared__ float As[8][128];
    __shared__ float Bs[8][128];
    int tid = threadIdx.x;
    int tx = tid & 15, ty = tid >> 4;
    float acc[8][8];
    #pragma unroll
    for (int i = 0; i < 8; i++)
        #pragma unroll
        for (int j = 0; j < 8; j++) acc[i][j] = 0.f;

    for (int k0 = 0; k0 < K; k0 += 8) {
        #pragma unroll
        for (int i = 0; i < 4; i++) {
            int lin = tid + i * 256;
            int kk = lin & 7, mm = lin >> 3;
            int gm = m0 + mm, gk = k0 + kk;
            As[kk][mm] = (gm < M && gk < K) ? A[(size_t)gm * K + gk] : 0.f;
        }
        #pragma unroll
        for (int i = 0; i < 4; i++) {
            int lin = tid + i * 256;
            int nn = lin & 127, kk = lin >> 7;
            int gn = n0 + nn, gk = k0 + kk;
            Bs[kk][nn] = (gn < N && gk < K) ? B[(size_t)gk * N + gn] : 0.f;
        }
        __syncthreads();
        #pragma unroll
        for (int kk = 0; kk < 8; kk++) {
            float a[8], b[8];
            *(float4*)&a[0] = *(const float4*)&As[kk][ty * 8];
            *(float4*)&a[4] = *(const float4*)&As[kk][ty * 8 + 4];
            *(float4*)&b[0] = *(const float4*)&Bs[kk][tx * 8];
            *(float4*)&b[4] = *(const float4*)&Bs[kk][tx * 8 + 4];
            #pragma unroll
            for (int i = 0; i < 8; i++)
                #pragma unroll
                for (int j = 0; j < 8; j++) acc[i][j] += a[i] * b[j];
        }
        __syncthreads();
    }

    #pragma unroll
    for (int i = 0; i < 8; i++) {
        int gm = m0 + ty * 8 + i;
        if (gm >= M) continue;
        #pragma unroll
        for (int j = 0; j < 8; j++) {
            int gn = n0 + tx * 8 + j;
            if (gn >= N) continue;
            float val = acc[i][j];
            if (mode == 0) {
                C[(size_t)gm * N + gn] = alpha * val;
            } else if (mode == 2) {
                C[(size_t)gm * N + gn] = val + bias[gn] + addx[(size_t)gm * N + gn];
            } else { // mode 1: qkv scatter
                int b_  = gm >> 13;
                int n_  = gm & 8191;
                int sec = gn >> 9;
                int cc  = gn & 511;
                int h_  = cc >> 6;
                int dh  = cc & 63;
                size_t idx = ((((size_t)b_ * H_ + h_) * NTOK) + n_) * DH_ + dh;
                if (sec == 0)      qp[idx] = val * 0.125f;
                else if (sec == 1) kp[idx] = val;
                else               vp[idx] = val;
            }
        }
    }
}

// ---------------- landmark means ----------------
__global__ void landmark_kernel(const float* __restrict__ q, const float* __restrict__ k,
                                float* __restrict__ ql, float* __restrict__ kl) {
    int bh = blockIdx.x, m = blockIdx.y;
    int dh = threadIdx.x;                  // 64 threads
    size_t base = ((size_t)bh * NTOK + (size_t)m * LSEG) * DH_ + dh;
    float aq = 0.f, ak = 0.f;
    #pragma unroll
    for (int i = 0; i < LSEG; i++) {
        aq += q[base + (size_t)i * DH_];
        ak += k[base + (size_t)i * DH_];
    }
    size_t o = ((size_t)bh * MLM + m) * DH_ + dh;
    ql[o] = aq * (1.f / LSEG);
    kl[o] = ak * (1.f / LSEG);
}

// ---------------- attn2 = softmax(q_l @ k_l^T) ----------------
__global__ void attn2_kernel(const float* __restrict__ ql, const float* __restrict__ kl,
                             float* __restrict__ X) {
    int bh = blockIdx.x, m = blockIdx.y;
    int j = threadIdx.x;                   // 256 threads
    __shared__ float qrow[DH_];
    __shared__ float wsum[8];
    if (j < DH_) qrow[j] = ql[((size_t)bh * MLM + m) * DH_ + j];
    __syncthreads();
    const float* kr = kl + ((size_t)bh * MLM + j) * DH_;
    float s = 0.f;
    #pragma unroll
    for (int d = 0; d < DH_; d++) s += qrow[d] * __ldg(&kr[d]);
    float e = __expf(s);
    float t = e;
    #pragma unroll
    for (int o = 16; o > 0; o >>= 1) t += __shfl_xor_sync(0xffffffffu, t, o);
    if ((j & 31) == 0) wsum[j >> 5] = t;
    __syncthreads();
    float S = 0.f;
    #pragma unroll
    for (int w = 0; w < 8; w++) S += wsum[w];
    X[((size_t)bh * MLM + m) * MLM + j] = e / S;
}

// ---------------- pinv helpers ----------------
__global__ void initmax_kernel(unsigned* mb) { mb[0] = 0u; mb[1] = 0u; }

__global__ void rowcol_kernel(const float* __restrict__ X, unsigned* mb) {
    int bh = blockIdx.x;
    int i = threadIdx.x;                   // 256 threads
    const float* Xm = X + (size_t)bh * MLM * MLM;
    float rs = 0.f, cs = 0.f;
    for (int j = 0; j < MLM; j++) {
        rs += fabsf(Xm[(size_t)i * MLM + j]);
        cs += fabsf(Xm[(size_t)j * MLM + i]);
    }
    #pragma unroll
    for (int o = 16; o > 0; o >>= 1) {
        rs = fmaxf(rs, __shfl_xor_sync(0xffffffffu, rs, o));
        cs = fmaxf(cs, __shfl_xor_sync(0xffffffffu, cs, o));
    }
    __shared__ float shr[8], shc[8];
    int w = i >> 5;
    if ((i & 31) == 0) { shr[w] = rs; shc[w] = cs; }
    __syncthreads();
    if (i == 0) {
        float mr = shr[0], mc = shc[0];
        #pragma unroll
        for (int k2 = 1; k2 < 8; k2++) { mr = fmaxf(mr, shr[k2]); mc = fmaxf(mc, shc[k2]); }
        atomicMax(&mb[0], __float_as_uint(mr));  // values >= 0: uint order == float order
        atomicMax(&mb[1], __float_as_uint(mc));
    }
}

__global__ void zinit_kernel(const float* __restrict__ X, float* __restrict__ Z,
                             const unsigned* __restrict__ mb) {
    float denom = __uint_as_float(mb[0]) * __uint_as_float(mb[1]);
    float inv = 1.f / denom;
    size_t idx = (size_t)blockIdx.x * 256 + threadIdx.x;   // over 32*256*256
    int bh = (int)(idx >> 16);
    int r = (int)((idx >> 8) & 255);
    int c = (int)(idx & 255);
    Z[idx] = X[((size_t)bh << 16) + ((size_t)c << 8) + r] * inv;
}

__global__ void diagsub_kernel(float* __restrict__ dst, const float* __restrict__ src, float c) {
    size_t idx = (size_t)blockIdx.x * 256 + threadIdx.x;
    int r = (int)((idx >> 8) & 255);
    int cc = (int)(idx & 255);
    dst[idx] = (r == cc ? c : 0.f) - src[idx];
}

// ---------------- attn3 @ v (streaming softmax over n) ----------------
__global__ void attn3v_kernel(const float* __restrict__ ql, const float* __restrict__ k,
                              const float* __restrict__ v, float* __restrict__ out) {
    // grid (BH, 8), block 128: 32 queries x 4 lanes of 16 dims
    int bh = blockIdx.x, qg = blockIdx.y;
    int tid = threadIdx.x;
    int q = tid >> 2, s = tid & 3;
    int m = qg * 32 + q;
    __shared__ float ks[64][64];
    __shared__ float vs[64][64];
    float qr[16];
    const float* qlp = ql + ((size_t)bh * MLM + m) * DH_ + s * 16;
    #pragma unroll
    for (int j = 0; j < 16; j++) qr[j] = qlp[j];
    float acc[16];
    #pragma unroll
    for (int j = 0; j < 16; j++) acc[j] = 0.f;
    float lsum = 0.f;
    const float* kbase = k + (size_t)bh * NTOK * DH_;
    const float* vbase = v + (size_t)bh * NTOK * DH_;

    for (int nt = 0; nt < NTOK; nt += 64) {
        __syncthreads();
        #pragma unroll
        for (int i = 0; i < 8; i++) {
            int f4 = tid + i * 128;
            int row = f4 >> 4, c4 = f4 & 15;
            ((float4*)ks)[f4] = ((const float4*)(kbase + (size_t)(nt + row) * DH_))[c4];
            ((float4*)vs)[f4] = ((const float4*)(vbase + (size_t)(nt + row) * DH_))[c4];
        }
        __syncthreads();
        #pragma unroll 4
        for (int n = 0; n < 64; n++) {
            const float* kr = &ks[n][s * 16];
            float p = 0.f;
            #pragma unroll
            for (int j = 0; j < 16; j++) p += qr[j] * kr[j];
            p += __shfl_xor_sync(0xffffffffu, p, 1);
            p += __shfl_xor_sync(0xffffffffu, p, 2);
            float e = __expf(p);   // scores are tiny (|s| < ~1.5): no max-subtraction needed
            lsum += e;
            const float* vr = &vs[n][s * 16];
            #pragma unroll
            for (int j = 0; j < 16; j++) acc[j] += e * vr[j];
        }
    }
    float invl = 1.f / lsum;
    float* op = out + ((size_t)bh * MLM + m) * DH_ + s * 16;
    #pragma unroll
    for (int j = 0; j < 16; j++) op[j] = acc[j] * invl;
}

// ---------------- depthwise conv (kernel 33 along n), writes O ----------------
__global__ void conv_kernel(const float* __restrict__ v, const float* __restrict__ ker,
                            float* __restrict__ O) {
    // grid (64 ntiles, H_, B_), 256 threads
    int nt = blockIdx.x, h = blockIdx.y, b = blockIdx.z;
    int n0 = nt * 128;
    __shared__ float vsh[160][64];
    __shared__ float kw[KER_];
    int tid = threadIdx.x;
    if (tid < KER_) kw[tid] = ker[h * KER_ + tid];
    const float* vb = v + ((size_t)b * H_ + h) * NTOK * DH_;
    #pragma unroll
    for (int i = 0; i < 10; i++) {
        int f4 = tid + i * 256;
        int row = f4 >> 4, c4 = f4 & 15;
        int n = n0 - 16 + row;
        float4 val = make_float4(0.f, 0.f, 0.f, 0.f);
        if (n >= 0 && n < NTOK) val = ((const float4*)(vb + (size_t)n * DH_))[c4];
        ((float4*)vsh)[f4] = val;
    }
    __syncthreads();
    int dh = tid & 63, g = tid >> 6;       // g: 0..3
    for (int ii = 0; ii < 32; ii++) {
        int nn = g * 32 + ii;
        float o = 0.f;
        #pragma unroll
        for (int t = 0; t < KER_; t++) o += kw[t] * vsh[nn + t][dh];
        O[((size_t)b * NTOK + (n0 + nn)) * D_ + h * DH_ + dh] = o;
    }
}

// ---------------- attn1 apply: O += softmax(q @ k_l^T) @ Y ----------------
__global__ void attn1_kernel(const float* __restrict__ q, const float* __restrict__ kl,
                             const float* __restrict__ Y, float* __restrict__ O) {
    // grid (32 chunks, H_, B_), 256 threads, dynamic shared
    extern __shared__ float sh[];
    float* kls   = sh;                       // 256*65 (padded vs bank conflicts)
    float* Ys    = kls + 256 * 65;           // 256*64
    float* qrow  = Ys + 256 * 64;            // 64
    float* ps    = qrow + 64;                // 256
    float* wsum  = ps + 256;                 // 8
    float* opart = wsum + 8;                 // 256
    int chunk = blockIdx.x, h = blockIdx.y, b = blockIdx.z;
    int bh = b * H_ + h;
    int tid = threadIdx.x;
    for (int i = tid; i < MLM * DH_; i += 256) {
        int r = i >> 6, c = i & 63;
        kls[r * 65 + c] = kl[((size_t)bh * MLM + r) * DH_ + c];
        Ys[i] = Y[(size_t)bh * MLM * DH_ + i];
    }
    __syncthreads();
    int n0 = chunk * 256;
    const float* qb = q + (size_t)bh * NTOK * DH_;
    int wid = tid >> 5, lane = tid & 31;
    int g = tid >> 6, dh = tid & 63;
    for (int nn = 0; nn < 256; nn++) {
        int n = n0 + nn;
        if (tid < 64) qrow[tid] = qb[(size_t)n * DH_ + tid];
        __syncthreads();
        const float* kr = &kls[tid * 65];
        float s = 0.f;
        #pragma unroll
        for (int d = 0; d < 64; d++) s += qrow[d] * kr[d];
        float e = __expf(s);
        ps[tid] = e;
        float t = e;
        #pragma unroll
        for (int o = 16; o > 0; o >>= 1) t += __shfl_xor_sync(0xffffffffu, t, o);
        if (lane == 0) wsum[wid] = t;
        __syncthreads();
        float S = 0.f;
        #pragma unroll
        for (int w = 0; w < 8; w++) S += wsum[w];
        const float* pp = &ps[g * 64];
        const float* Yp = &Ys[(size_t)g * 64 * 64 + dh];
        float o = 0.f;
        #pragma unroll 16
        for (int jj = 0; jj < 64; jj++) o += pp[jj] * Yp[(size_t)jj * 64];
        opart[tid] = o;
        __syncthreads();
        if (tid < 64) {
            float oo = opart[tid] + opart[64 + tid] + opart[128 + tid] + opart[192 + tid];
            O[((size_t)b * NTOK + n) * D_ + h * DH_ + tid] += oo / S;
        }
        __syncthreads();
    }
}

// ---------------- host launcher ----------------
extern "C" void kernel_launch(void* const* d_in, const int* in_sizes, int n_in,
                              void* d_out, int out_size) {
    const float* x      = (const float*)d_in[0];
    const float* gamma  = (const float*)d_in[1];
    const float* beta   = (const float*)d_in[2];
    const float* w_qkv  = (const float*)d_in[3];
    const float* res_k  = (const float*)d_in[4];
    const float* w_out  = (const float*)d_in[5];
    const float* b_out  = (const float*)d_in[6];
    float* out = (float*)d_out;

    float *normed, *q, *k, *v, *ql, *kl, *X, *Za, *Zb, *XZ, *W, *W2, *A3V, *Y, *O;
    unsigned* mb;
    cudaGetSymbolAddress((void**)&normed, g_normed);
    cudaGetSymbolAddress((void**)&q,  g_q);
    cudaGetSymbolAddress((void**)&k,  g_k);
    cudaGetSymbolAddress((void**)&v,  g_v);
    cudaGetSymbolAddress((void**)&ql, g_ql);
    cudaGetSymbolAddress((void**)&kl, g_kl);
    cudaGetSymbolAddress((void**)&X,  g_X);
    cudaGetSymbolAddress((void**)&Za, g_Za);
    cudaGetSymbolAddress((void**)&Zb, g_Zb);
    cudaGetSymbolAddress((void**)&XZ, g_XZ);
    cudaGetSymbolAddress((void**)&W,  g_W);
    cudaGetSymbolAddress((void**)&W2, g_W2);
    cudaGetSymbolAddress((void**)&A3V, g_A3V);
    cudaGetSymbolAddress((void**)&Y,  g_Y);
    cudaGetSymbolAddress((void**)&O,  g_O);
    cudaGetSymbolAddress((void**)&mb, g_maxbits);

    const int attn1_smem = (256 * 65 + 256 * 64 + 64 + 256 + 8 + 256) * (int)sizeof(float);
    cudaFuncSetAttribute(attn1_kernel, cudaFuncAttributeMaxDynamicSharedMemorySize, attn1_smem);

    // 1. LayerNorm
    ln_kernel<<<B_ * NTOK, 256>>>(x, gamma, beta, normed);

    // 2. QKV GEMM with head scatter
    sgemm_kernel<<<dim3(12, 256, 1), 256>>>(normed, w_qkv, nullptr,
        B_ * NTOK, 3 * D_, D_, 0, 0, 0, 1.f, 1, nullptr, nullptr, q, k, v);

    // 3. Landmarks
    landmark_kernel<<<dim3(BH, MLM), 64>>>(q, k, ql, kl);

    // 4. attn2
    attn2_kernel<<<dim3(BH, MLM), 256>>>(ql, kl, X);

    // 5. pinv init
    initmax_kernel<<<1, 1>>>(mb);
    rowcol_kernel<<<BH, 256>>>(X, mb);
    zinit_kernel<<<8192, 256>>>(X, Za, mb);

    // 6. Newton iterations: z = 0.25 z (13I - xz(15I - xz(7I - xz)))
    float* zc = Za; float* zn = Zb;
    const size_t sM = (size_t)MLM * MLM;
    for (int it = 0; it < 6; it++) {
        sgemm_kernel<<<dim3(2, 2, BH), 256>>>(X, zc, XZ, MLM, MLM, MLM, sM, sM, sM,
            1.f, 0, nullptr, nullptr, nullptr, nullptr, nullptr);
        diagsub_kernel<<<8192, 256>>>(W, XZ, 7.f);
        sgemm_kernel<<<dim3(2, 2, BH), 256>>>(XZ, W, W2, MLM, MLM, MLM, sM, sM, sM,
            1.f, 0, nullptr, nullptr, nullptr, nullptr, nullptr);
        diagsub_kernel<<<8192, 256>>>(W, W2, 15.f);
        sgemm_kernel<<<dim3(2, 2, BH), 256>>>(XZ, W, W2, MLM, MLM, MLM, sM, sM, sM,
            1.f, 0, nullptr, nullptr, nullptr, nullptr, nullptr);
        diagsub_kernel<<<8192, 256>>>(W, W2, 13.f);
        sgemm_kernel<<<dim3(2, 2, BH), 256>>>(zc, W, zn, MLM, MLM, MLM, sM, sM, sM,
            0.25f, 0, nullptr, nullptr, nullptr, nullptr, nullptr);
        float* tmp = zc; zc = zn; zn = tmp;
    }

    // 7. attn3 @ v
    attn3v_kernel<<<dim3(BH, 8), 128>>>(ql, k, v, A3V);

    // 8. Y = pinv(attn2) @ (attn3 @ v)
    sgemm_kernel<<<dim3(1, 2, BH), 256>>>(zc, A3V, Y, MLM, DH_, MLM,
        sM, (size_t)MLM * DH_, (size_t)MLM * DH_,
        1.f, 0, nullptr, nullptr, nullptr, nullptr, nullptr);

    // 9. conv writes O
    conv_kernel<<<dim3(64, H_, B_), 256>>>(v, res_k, O);

    // 10. attn1 applied, accumulated into O
    attn1_kernel<<<dim3(32, H_, B_), 256, attn1_smem>>>(q, kl, Y, O);

    // 11. out = x + O @ w_out + b_out
    sgemm_kernel<<<dim3(4, 256, 1), 256>>>(O, w_out, out, B_ * NTOK, D_, D_, 0, 0, 0,
        1.f, 2, x, b_out, nullptr, nullptr, nullptr);
}